// round 2
// baseline (speedup 1.0000x reference)
#include <cuda_runtime.h>
#include <stdint.h>

// =====================================================================
// EBSW loss: reproduce JAX threefry RNG + IMH chain + sliced W2 distances
// R2: register/shfl bitonic sort (V=16/thread), smem only for j>=512
// =====================================================================

#define PARTITIONABLE 1   // modern JAX default: jax_threefry_partitionable=True

static const int BATCH = 64;
static const int NPTS  = 4096;
static const int DIMS  = 3;
static const int LPROJ = 128;

__device__ float g_theta[LPROJ][BATCH][DIMS]; // normalized candidate thetas per step
__device__ float g_logu [LPROJ][BATCH];       // log(uniform) for acceptance, rows 1..127
__device__ float g_dist [BATCH][LPROJ];       // cand_dist[b][l]

// ---------------------------------------------------------------------
// threefry2x32 (20 rounds), exactly as JAX/Random123
// ---------------------------------------------------------------------
__device__ __forceinline__ uint2 tf2x32(unsigned k0, unsigned k1,
                                        unsigned x0, unsigned x1) {
    unsigned ks2 = k0 ^ k1 ^ 0x1BD11BDAu;
    x0 += k0; x1 += k1;
#define TFR(r) { x0 += x1; x1 = (x1 << (r)) | (x1 >> (32 - (r))); x1 ^= x0; }
    TFR(13) TFR(15) TFR(26) TFR(6)
    x0 += k1; x1 += ks2 + 1u;
    TFR(17) TFR(29) TFR(16) TFR(24)
    x0 += ks2; x1 += k0 + 2u;
    TFR(13) TFR(15) TFR(26) TFR(6)
    x0 += k0; x1 += k1 + 3u;
    TFR(17) TFR(29) TFR(16) TFR(24)
    x0 += k1; x1 += ks2 + 4u;
    TFR(13) TFR(15) TFR(26) TFR(6)
    x0 += ks2; x1 += k0 + 5u;
#undef TFR
    return make_uint2(x0, x1);
}

// ---------------------------------------------------------------------
// XLA ErfInv32 polynomial (Giles), op-ordering matched (no FMA contraction)
// ---------------------------------------------------------------------
__device__ __forceinline__ float xla_erfinv(float x) {
    float xx = __fmul_rn(x, x);
    float w  = -log1pf(-xx);
    float p;
    if (w < 5.0f) {
        w = __fadd_rn(w, -2.5f);
        p = 2.81022636e-08f;
        p = __fadd_rn( 3.43273939e-07f, __fmul_rn(p, w));
        p = __fadd_rn(-3.5233877e-06f,  __fmul_rn(p, w));
        p = __fadd_rn(-4.39150654e-06f, __fmul_rn(p, w));
        p = __fadd_rn( 0.00021858087f,  __fmul_rn(p, w));
        p = __fadd_rn(-0.00125372503f,  __fmul_rn(p, w));
        p = __fadd_rn(-0.00417768164f,  __fmul_rn(p, w));
        p = __fadd_rn( 0.246640727f,    __fmul_rn(p, w));
        p = __fadd_rn( 1.50140941f,     __fmul_rn(p, w));
    } else {
        w = __fadd_rn(__fsqrt_rn(w), -3.0f);
        p = -0.000200214257f;
        p = __fadd_rn( 0.000100950558f, __fmul_rn(p, w));
        p = __fadd_rn( 0.00134934322f,  __fmul_rn(p, w));
        p = __fadd_rn(-0.00367342844f,  __fmul_rn(p, w));
        p = __fadd_rn( 0.00573950773f,  __fmul_rn(p, w));
        p = __fadd_rn(-0.0076224613f,   __fmul_rn(p, w));
        p = __fadd_rn( 0.00943887047f,  __fmul_rn(p, w));
        p = __fadd_rn( 1.00167406f,     __fmul_rn(p, w));
        p = __fadd_rn( 2.83297682f,     __fmul_rn(p, w));
    }
    return __fmul_rn(p, x);
}

// bits -> float in [0,1): bitcast(bits>>9 | 0x3f800000) - 1   (exact ops)
__device__ __forceinline__ float bits_to_unit(unsigned bits) {
    return __uint_as_float((bits >> 9) | 0x3f800000u) - 1.0f;
}

// ---------------------------------------------------------------------
// RNG kernel: one block per chain step l. 192 threads.
// ---------------------------------------------------------------------
__global__ void ebsw_rng_kernel() {
    const int l = blockIdx.x;
    const int t = threadIdx.x;      // 0..191
    __shared__ float raw[BATCH * DIMS];

    uint2 kl = tf2x32(0u, 42u, 0u, (unsigned)l);
    uint2 ka, kb;
    if (l == 0) {
        ka = kl; kb = make_uint2(0u, 0u);
    } else {
#if PARTITIONABLE
        ka = tf2x32(kl.x, kl.y, 0u, 0u);
        kb = tf2x32(kl.x, kl.y, 0u, 1u);
#else
        uint2 p0 = tf2x32(kl.x, kl.y, 0u, 2u);
        uint2 p1 = tf2x32(kl.x, kl.y, 1u, 3u);
        ka = make_uint2(p0.x, p1.x);
        kb = make_uint2(p0.y, p1.y);
#endif
    }

    unsigned bits;
#if PARTITIONABLE
    { uint2 r = tf2x32(ka.x, ka.y, 0u, (unsigned)t); bits = r.x ^ r.y; }
#else
    if (t < 96) { uint2 r = tf2x32(ka.x, ka.y, (unsigned)t, (unsigned)(96 + t)); bits = r.x; }
    else        { uint2 r = tf2x32(ka.x, ka.y, (unsigned)(t - 96), (unsigned)t); bits = r.y; }
#endif
    const float LO = -0.99999994f;          // nextafterf(-1,0)
    float f = bits_to_unit(bits);
    float u = __fadd_rn(__fmul_rn(f, 2.0f), LO);
    u = fmaxf(LO, u);
    raw[t] = __fmul_rn(1.41421356237309515f, xla_erfinv(u));
    __syncthreads();

    if (t < BATCH) {
        float v0 = raw[t * 3 + 0], v1 = raw[t * 3 + 1], v2 = raw[t * 3 + 2];
        float s  = __fadd_rn(__fadd_rn(__fmul_rn(v0, v0), __fmul_rn(v1, v1)),
                             __fmul_rn(v2, v2));
        float r  = __fsqrt_rn(s);
        g_theta[l][t][0] = __fdiv_rn(v0, r);
        g_theta[l][t][1] = __fdiv_rn(v1, r);
        g_theta[l][t][2] = __fdiv_rn(v2, r);

        if (l >= 1) {
            unsigned ub;
#if PARTITIONABLE
            { uint2 r2 = tf2x32(kb.x, kb.y, 0u, (unsigned)t); ub = r2.x ^ r2.y; }
#else
            if (t < 32) { uint2 r2 = tf2x32(kb.x, kb.y, (unsigned)t, (unsigned)(32 + t)); ub = r2.x; }
            else        { uint2 r2 = tf2x32(kb.x, kb.y, (unsigned)(t - 32), (unsigned)t); ub = r2.y; }
#endif
            g_logu[l][t] = logf(bits_to_unit(ub));
        }
    }
}

// ---------------------------------------------------------------------
// Distance kernel: one CTA per (b, l), 512 threads = two 256-thread
// groups (group 0 sorts xp, group 1 sorts yp). V=16 elems/thread in
// registers; bitonic network with:
//   j <  16            : in-register compare-exchange
//   16 <= j < 512      : shfl_xor butterfly
//   j >= 512 (6 passes): smem exchange (stride-17 padded, conflict-free)
// ---------------------------------------------------------------------
static const int TPB = 512;
static const int TPA = 256;    // threads per array
static const int V   = 16;     // elements per thread
static const int PAD = 17;     // padded row stride (conflict-free)

__global__ __launch_bounds__(TPB) void ebsw_dist_kernel(
        const float* __restrict__ x, const float* __restrict__ y) {
    __shared__ float s[2 * TPA * PAD];   // 8704 floats = 34,816 B
    const int blk = blockIdx.x;
    const int b = blk >> 7;
    const int l = blk & (LPROJ - 1);

    const float t0 = g_theta[l][b][0];
    const float t1 = g_theta[l][b][1];
    const float t2 = g_theta[l][b][2];

    const int tid = threadIdx.x;
    const int g   = tid >> 8;          // 0 -> x array, 1 -> y array
    const int lt  = tid & (TPA - 1);   // 0..255 within group
    float* buf = s + g * (TPA * PAD);

    // Stage projections into padded smem, coalesced per group
    const float* pb = (g == 0 ? x : y) + (size_t)b * NPTS * DIMS;
    for (int n = lt; n < NPTS; n += TPA) {
        int o = n * 3;
        buf[(n >> 4) * PAD + (n & 15)] =
            fmaf(pb[o], t0, fmaf(pb[o + 1], t1, pb[o + 2] * t2));
    }
    __syncthreads();

    // Load 16 contiguous elements into registers: i = lt*16 + v
    float r[V];
#pragma unroll
    for (int v = 0; v < V; ++v) r[v] = buf[lt * PAD + v];
    __syncthreads();   // protect staging buffer before first smem-exchange pass

    // Bitonic sort of 4096 elements
    for (int k = 2; k <= NPTS; k <<= 1) {
        for (int j = k >> 1; j > 0; j >>= 1) {
            if (j >= V) {
                const int  d       = j >> 4;                       // partner thread distance
                const bool up      = ((lt & (k >> 4)) == 0);
                const bool keepmin = (((lt & d) == 0) == up);
                if (d < 32) {
                    // intra-warp butterfly
#pragma unroll
                    for (int v = 0; v < V; ++v) {
                        float o = __shfl_xor_sync(0xffffffffu, r[v], d);
                        r[v] = keepmin ? fminf(r[v], o) : fmaxf(r[v], o);
                    }
                } else {
                    // cross-warp exchange via padded smem
#pragma unroll
                    for (int v = 0; v < V; ++v) buf[lt * PAD + v] = r[v];
                    __syncthreads();
                    const int p = (lt ^ d) * PAD;
#pragma unroll
                    for (int v = 0; v < V; ++v) {
                        float o = buf[p + v];
                        r[v] = keepmin ? fminf(r[v], o) : fmaxf(r[v], o);
                    }
                    __syncthreads();
                }
            } else {
                // in-register compare-exchange: pairs (v, v|j)
                const bool upk = (k >= V) ? ((lt & (k >> 4)) == 0) : false;
#pragma unroll
                for (int v = 0; v < V; ++v) {
                    if ((v & j) == 0) {
                        const int  w  = v | j;
                        const bool up = (k >= V) ? upk : ((v & k) == 0);
                        float a = r[v], c = r[w];
                        float mn = fminf(a, c), mx = fmaxf(a, c);
                        r[v] = up ? mn : mx;
                        r[w] = up ? mx : mn;
                    }
                }
            }
        }
    }

    // Write sorted values back (padded layout), then rank-matched reduce
#pragma unroll
    for (int v = 0; v < V; ++v) buf[lt * PAD + v] = r[v];
    __syncthreads();

    double acc = 0.0;
    for (int n = tid; n < NPTS; n += TPB) {
        int a = (n >> 4) * PAD + (n & 15);
        float d = s[a] - s[TPA * PAD + a];
        acc += (double)d * (double)d;
    }
#pragma unroll
    for (int off = 16; off; off >>= 1)
        acc += __shfl_down_sync(0xffffffffu, acc, off);
    __shared__ double wsum[TPB / 32];
    if ((threadIdx.x & 31) == 0) wsum[threadIdx.x >> 5] = acc;
    __syncthreads();
    if (threadIdx.x < TPB / 32) {
        double v = wsum[threadIdx.x];
#pragma unroll
        for (int off = (TPB / 32) / 2; off; off >>= 1)
            v += __shfl_down_sync(0xffffu, v, off);
        if (threadIdx.x == 0) g_dist[b][l] = (float)v;
    }
}

// ---------------------------------------------------------------------
// Chain + loss kernel
// ---------------------------------------------------------------------
__global__ void ebsw_chain_kernel(float* __restrict__ out) {
    const int b = threadIdx.x;      // 64 threads
    __shared__ double sh[BATCH];
    const float* db = g_dist[b];
    float dist_old = db[0];
    double acc = (double)dist_old;
    for (int l = 1; l < LPROJ; ++l) {
        float dn = db[l];
        float ar = fminf(0.0f, __fadd_rn(dn, -dist_old));
        if (g_logu[l][b] <= ar) dist_old = dn;   // accept
        acc += (double)dist_old;
    }
    sh[b] = sqrt(acc / (double)LPROJ);
    __syncthreads();
    if (b == 0) {
        double ssum = 0.0;
        for (int i = 0; i < BATCH; ++i) ssum += sh[i];
        out[0] = (float)(ssum / (double)BATCH);
    }
}

// ---------------------------------------------------------------------
extern "C" void kernel_launch(void* const* d_in, const int* in_sizes, int n_in,
                              void* d_out, int out_size) {
    const float* x = (const float*)d_in[0];
    const float* y = (const float*)d_in[1];
    float* out = (float*)d_out;

    ebsw_rng_kernel<<<LPROJ, BATCH * DIMS>>>();
    ebsw_dist_kernel<<<BATCH * LPROJ, TPB>>>(x, y);
    ebsw_chain_kernel<<<1, BATCH>>>(out);
}

// round 3
// speedup vs baseline: 2.7873x; 2.7873x over previous
#include <cuda_runtime.h>
#include <stdint.h>

// =====================================================================
// EBSW loss: JAX threefry RNG + IMH chain + sliced W2 distances
// R3: register bitonic with COMPILE-TIME strides (if constexpr recursion)
//     -> no local-memory spills (R2's bug: runtime-indexed reg array)
// =====================================================================

#define PARTITIONABLE 1

static const int BATCH = 64;
static const int NPTS  = 4096;
static const int DIMS  = 3;
static const int LPROJ = 128;

__device__ float g_theta[LPROJ][BATCH][DIMS];
__device__ float g_logu [LPROJ][BATCH];
__device__ float g_dist [BATCH][LPROJ];

// ---------------------------------------------------------------------
// threefry2x32 (20 rounds)
// ---------------------------------------------------------------------
__device__ __forceinline__ uint2 tf2x32(unsigned k0, unsigned k1,
                                        unsigned x0, unsigned x1) {
    unsigned ks2 = k0 ^ k1 ^ 0x1BD11BDAu;
    x0 += k0; x1 += k1;
#define TFR(r) { x0 += x1; x1 = (x1 << (r)) | (x1 >> (32 - (r))); x1 ^= x0; }
    TFR(13) TFR(15) TFR(26) TFR(6)
    x0 += k1; x1 += ks2 + 1u;
    TFR(17) TFR(29) TFR(16) TFR(24)
    x0 += ks2; x1 += k0 + 2u;
    TFR(13) TFR(15) TFR(26) TFR(6)
    x0 += k0; x1 += k1 + 3u;
    TFR(17) TFR(29) TFR(16) TFR(24)
    x0 += k1; x1 += ks2 + 4u;
    TFR(13) TFR(15) TFR(26) TFR(6)
    x0 += ks2; x1 += k0 + 5u;
#undef TFR
    return make_uint2(x0, x1);
}

__device__ __forceinline__ float xla_erfinv(float x) {
    float xx = __fmul_rn(x, x);
    float w  = -log1pf(-xx);
    float p;
    if (w < 5.0f) {
        w = __fadd_rn(w, -2.5f);
        p = 2.81022636e-08f;
        p = __fadd_rn( 3.43273939e-07f, __fmul_rn(p, w));
        p = __fadd_rn(-3.5233877e-06f,  __fmul_rn(p, w));
        p = __fadd_rn(-4.39150654e-06f, __fmul_rn(p, w));
        p = __fadd_rn( 0.00021858087f,  __fmul_rn(p, w));
        p = __fadd_rn(-0.00125372503f,  __fmul_rn(p, w));
        p = __fadd_rn(-0.00417768164f,  __fmul_rn(p, w));
        p = __fadd_rn( 0.246640727f,    __fmul_rn(p, w));
        p = __fadd_rn( 1.50140941f,     __fmul_rn(p, w));
    } else {
        w = __fadd_rn(__fsqrt_rn(w), -3.0f);
        p = -0.000200214257f;
        p = __fadd_rn( 0.000100950558f, __fmul_rn(p, w));
        p = __fadd_rn( 0.00134934322f,  __fmul_rn(p, w));
        p = __fadd_rn(-0.00367342844f,  __fmul_rn(p, w));
        p = __fadd_rn( 0.00573950773f,  __fmul_rn(p, w));
        p = __fadd_rn(-0.0076224613f,   __fmul_rn(p, w));
        p = __fadd_rn( 0.00943887047f,  __fmul_rn(p, w));
        p = __fadd_rn( 1.00167406f,     __fmul_rn(p, w));
        p = __fadd_rn( 2.83297682f,     __fmul_rn(p, w));
    }
    return __fmul_rn(p, x);
}

__device__ __forceinline__ float bits_to_unit(unsigned bits) {
    return __uint_as_float((bits >> 9) | 0x3f800000u) - 1.0f;
}

// ---------------------------------------------------------------------
// RNG kernel (unchanged — verified bit-exact, 4.8us)
// ---------------------------------------------------------------------
__global__ void ebsw_rng_kernel() {
    const int l = blockIdx.x;
    const int t = threadIdx.x;
    __shared__ float raw[BATCH * DIMS];

    uint2 kl = tf2x32(0u, 42u, 0u, (unsigned)l);
    uint2 ka, kb;
    if (l == 0) {
        ka = kl; kb = make_uint2(0u, 0u);
    } else {
#if PARTITIONABLE
        ka = tf2x32(kl.x, kl.y, 0u, 0u);
        kb = tf2x32(kl.x, kl.y, 0u, 1u);
#else
        uint2 p0 = tf2x32(kl.x, kl.y, 0u, 2u);
        uint2 p1 = tf2x32(kl.x, kl.y, 1u, 3u);
        ka = make_uint2(p0.x, p1.x);
        kb = make_uint2(p0.y, p1.y);
#endif
    }

    unsigned bits;
#if PARTITIONABLE
    { uint2 r = tf2x32(ka.x, ka.y, 0u, (unsigned)t); bits = r.x ^ r.y; }
#else
    if (t < 96) { uint2 r = tf2x32(ka.x, ka.y, (unsigned)t, (unsigned)(96 + t)); bits = r.x; }
    else        { uint2 r = tf2x32(ka.x, ka.y, (unsigned)(t - 96), (unsigned)t); bits = r.y; }
#endif
    const float LO = -0.99999994f;
    float f = bits_to_unit(bits);
    float u = __fadd_rn(__fmul_rn(f, 2.0f), LO);
    u = fmaxf(LO, u);
    raw[t] = __fmul_rn(1.41421356237309515f, xla_erfinv(u));
    __syncthreads();

    if (t < BATCH) {
        float v0 = raw[t * 3 + 0], v1 = raw[t * 3 + 1], v2 = raw[t * 3 + 2];
        float s  = __fadd_rn(__fadd_rn(__fmul_rn(v0, v0), __fmul_rn(v1, v1)),
                             __fmul_rn(v2, v2));
        float r  = __fsqrt_rn(s);
        g_theta[l][t][0] = __fdiv_rn(v0, r);
        g_theta[l][t][1] = __fdiv_rn(v1, r);
        g_theta[l][t][2] = __fdiv_rn(v2, r);

        if (l >= 1) {
            unsigned ub;
#if PARTITIONABLE
            { uint2 r2 = tf2x32(kb.x, kb.y, 0u, (unsigned)t); ub = r2.x ^ r2.y; }
#else
            if (t < 32) { uint2 r2 = tf2x32(kb.x, kb.y, (unsigned)t, (unsigned)(32 + t)); ub = r2.x; }
            else        { uint2 r2 = tf2x32(kb.x, kb.y, (unsigned)(t - 32), (unsigned)t); ub = r2.y; }
#endif
            g_logu[l][t] = logf(bits_to_unit(ub));
        }
    }
}

// ---------------------------------------------------------------------
// Distance kernel, fully compile-time bitonic network
// ---------------------------------------------------------------------
static const int TPB = 512;
static const int TPA = 256;
static const int V   = 16;
static const int PAD = 17;

__device__ __forceinline__ void cx(float& a, float& b, bool up) {
    float mn = fminf(a, b), mx = fmaxf(a, b);
    a = up ? mn : mx;
    b = up ? mx : mn;
}

// intra-register merge, strides J..1, uniform direction
template<int J>
__device__ __forceinline__ void merge_reg(float* r, bool up) {
    if constexpr (J >= 1) {
#pragma unroll
        for (int v = 0; v < V; ++v)
            if ((v & J) == 0) cx(r[v], r[v | J], up);
        merge_reg<J / 2>(r, up);
    }
}

// intra-register sort phase for block size K<=8: direction = ((v&K)==0)
template<int K, int J>
__device__ __forceinline__ void sort_reg_small(float* r) {
    if constexpr (J >= 1) {
#pragma unroll
        for (int v = 0; v < V; ++v)
            if ((v & J) == 0) cx(r[v], r[v | J], ((v & K) == 0));
        sort_reg_small<K, J / 2>(r);
    }
}

// cross-thread exchange at thread distance D (compile-time)
template<int D>
__device__ __forceinline__ void exchange_step(float* r, float* buf, int lt, bool up) {
    const bool keepmin = (((lt & D) == 0) == up);
    if constexpr (D < 32) {
#pragma unroll
        for (int v = 0; v < V; ++v) {
            float o = __shfl_xor_sync(0xffffffffu, r[v], D);
            r[v] = keepmin ? fminf(r[v], o) : fmaxf(r[v], o);
        }
    } else {
#pragma unroll
        for (int v = 0; v < V; ++v) buf[lt * PAD + v] = r[v];
        __syncthreads();
        const int p = (lt ^ D) * PAD;
#pragma unroll
        for (int v = 0; v < V; ++v) {
            float o = buf[p + v];
            r[v] = keepmin ? fminf(r[v], o) : fmaxf(r[v], o);
        }
        __syncthreads();
    }
}

// full merge for block size k = KK*16: thread-level strides D..1, then regs
template<int KK, int D>
__device__ __forceinline__ void merge_chain(float* r, float* buf, int lt, bool up) {
    if constexpr (D >= 1) {
        exchange_step<D>(r, buf, lt, up);
        merge_chain<KK, D / 2>(r, buf, lt, up);
    } else {
        merge_reg<V / 2>(r, up);
    }
}

__global__ __launch_bounds__(TPB) void ebsw_dist_kernel(
        const float* __restrict__ x, const float* __restrict__ y) {
    __shared__ float s[2 * TPA * PAD];
    const int blk = blockIdx.x;
    const int b = blk >> 7;
    const int l = blk & (LPROJ - 1);

    const float t0 = g_theta[l][b][0];
    const float t1 = g_theta[l][b][1];
    const float t2 = g_theta[l][b][2];

    const int tid = threadIdx.x;
    const int g   = tid >> 8;
    const int lt  = tid & (TPA - 1);
    float* buf = s + g * (TPA * PAD);

    const float* pb = (g == 0 ? x : y) + (size_t)b * NPTS * DIMS;
    for (int n = lt; n < NPTS; n += TPA) {
        int o = n * 3;
        buf[(n >> 4) * PAD + (n & 15)] =
            fmaf(pb[o], t0, fmaf(pb[o + 1], t1, pb[o + 2] * t2));
    }
    __syncthreads();

    float r[V];
#pragma unroll
    for (int v = 0; v < V; ++v) r[v] = buf[lt * PAD + v];

    // ---- bitonic sort of 4096 = 256 threads x 16 regs ----
    // k = 2, 4, 8 : purely in-register, per-element direction
    sort_reg_small<2, 1>(r);
    sort_reg_small<4, 2>(r);
    sort_reg_small<8, 4>(r);
    // k = 16 : in-register, per-thread direction
    { bool up = ((lt & 1) == 0);   merge_reg<V / 2>(r, up); }
    // k = 32 .. 4096 : cross-thread merges (KK = k/16)
    { bool up = ((lt & 2)   == 0); merge_chain<2,   1  >(r, buf, lt, up); }
    { bool up = ((lt & 4)   == 0); merge_chain<4,   2  >(r, buf, lt, up); }
    { bool up = ((lt & 8)   == 0); merge_chain<8,   4  >(r, buf, lt, up); }
    { bool up = ((lt & 16)  == 0); merge_chain<16,  8  >(r, buf, lt, up); }
    { bool up = ((lt & 32)  == 0); merge_chain<32,  16 >(r, buf, lt, up); }
    { bool up = ((lt & 64)  == 0); merge_chain<64,  32 >(r, buf, lt, up); }
    { bool up = ((lt & 128) == 0); merge_chain<128, 64 >(r, buf, lt, up); }
    {                              merge_chain<256, 128>(r, buf, lt, true); }

    // write back sorted, reduce sum of squared rank differences
#pragma unroll
    for (int v = 0; v < V; ++v) buf[lt * PAD + v] = r[v];
    __syncthreads();

    double acc = 0.0;
    for (int n = tid; n < NPTS; n += TPB) {
        int a = (n >> 4) * PAD + (n & 15);
        float d = s[a] - s[TPA * PAD + a];
        acc += (double)d * (double)d;
    }
#pragma unroll
    for (int off = 16; off; off >>= 1)
        acc += __shfl_down_sync(0xffffffffu, acc, off);
    __shared__ double wsum[TPB / 32];
    if ((threadIdx.x & 31) == 0) wsum[threadIdx.x >> 5] = acc;
    __syncthreads();
    if (threadIdx.x < TPB / 32) {
        double v = wsum[threadIdx.x];
#pragma unroll
        for (int off = (TPB / 32) / 2; off; off >>= 1)
            v += __shfl_down_sync(0xffffu, v, off);
        if (threadIdx.x == 0) g_dist[b][l] = (float)v;
    }
}

// ---------------------------------------------------------------------
// Chain + loss kernel (unchanged)
// ---------------------------------------------------------------------
__global__ void ebsw_chain_kernel(float* __restrict__ out) {
    const int b = threadIdx.x;
    __shared__ double sh[BATCH];
    const float* db = g_dist[b];
    float dist_old = db[0];
    double acc = (double)dist_old;
    for (int l = 1; l < LPROJ; ++l) {
        float dn = db[l];
        float ar = fminf(0.0f, __fadd_rn(dn, -dist_old));
        if (g_logu[l][b] <= ar) dist_old = dn;
        acc += (double)dist_old;
    }
    sh[b] = sqrt(acc / (double)LPROJ);
    __syncthreads();
    if (b == 0) {
        double ssum = 0.0;
        for (int i = 0; i < BATCH; ++i) ssum += sh[i];
        out[0] = (float)(ssum / (double)BATCH);
    }
}

// ---------------------------------------------------------------------
extern "C" void kernel_launch(void* const* d_in, const int* in_sizes, int n_in,
                              void* d_out, int out_size) {
    const float* x = (const float*)d_in[0];
    const float* y = (const float*)d_in[1];
    float* out = (float*)d_out;

    ebsw_rng_kernel<<<LPROJ, BATCH * DIMS>>>();
    ebsw_dist_kernel<<<BATCH * LPROJ, TPB>>>(x, y);
    ebsw_chain_kernel<<<1, BATCH>>>(out);
}

// round 4
// speedup vs baseline: 4.8877x; 1.7536x over previous
#include <cuda_runtime.h>
#include <stdint.h>

// =====================================================================
// EBSW loss: JAX threefry RNG + IMH chain + sliced W2 distances
// R4: V=32 register bitonic (50 reg / 25 shfl / 3 smem phases),
//     256 threads/CTA (two 128-thread groups, one per array)
// =====================================================================

#define PARTITIONABLE 1

static const int BATCH = 64;
static const int NPTS  = 4096;
static const int DIMS  = 3;
static const int LPROJ = 128;

__device__ float g_theta[LPROJ][BATCH][DIMS];
__device__ float g_logu [LPROJ][BATCH];
__device__ float g_dist [BATCH][LPROJ];

// ---------------------------------------------------------------------
// threefry2x32 (20 rounds)
// ---------------------------------------------------------------------
__device__ __forceinline__ uint2 tf2x32(unsigned k0, unsigned k1,
                                        unsigned x0, unsigned x1) {
    unsigned ks2 = k0 ^ k1 ^ 0x1BD11BDAu;
    x0 += k0; x1 += k1;
#define TFR(r) { x0 += x1; x1 = (x1 << (r)) | (x1 >> (32 - (r))); x1 ^= x0; }
    TFR(13) TFR(15) TFR(26) TFR(6)
    x0 += k1; x1 += ks2 + 1u;
    TFR(17) TFR(29) TFR(16) TFR(24)
    x0 += ks2; x1 += k0 + 2u;
    TFR(13) TFR(15) TFR(26) TFR(6)
    x0 += k0; x1 += k1 + 3u;
    TFR(17) TFR(29) TFR(16) TFR(24)
    x0 += k1; x1 += ks2 + 4u;
    TFR(13) TFR(15) TFR(26) TFR(6)
    x0 += ks2; x1 += k0 + 5u;
#undef TFR
    return make_uint2(x0, x1);
}

__device__ __forceinline__ float xla_erfinv(float x) {
    float xx = __fmul_rn(x, x);
    float w  = -log1pf(-xx);
    float p;
    if (w < 5.0f) {
        w = __fadd_rn(w, -2.5f);
        p = 2.81022636e-08f;
        p = __fadd_rn( 3.43273939e-07f, __fmul_rn(p, w));
        p = __fadd_rn(-3.5233877e-06f,  __fmul_rn(p, w));
        p = __fadd_rn(-4.39150654e-06f, __fmul_rn(p, w));
        p = __fadd_rn( 0.00021858087f,  __fmul_rn(p, w));
        p = __fadd_rn(-0.00125372503f,  __fmul_rn(p, w));
        p = __fadd_rn(-0.00417768164f,  __fmul_rn(p, w));
        p = __fadd_rn( 0.246640727f,    __fmul_rn(p, w));
        p = __fadd_rn( 1.50140941f,     __fmul_rn(p, w));
    } else {
        w = __fadd_rn(__fsqrt_rn(w), -3.0f);
        p = -0.000200214257f;
        p = __fadd_rn( 0.000100950558f, __fmul_rn(p, w));
        p = __fadd_rn( 0.00134934322f,  __fmul_rn(p, w));
        p = __fadd_rn(-0.00367342844f,  __fmul_rn(p, w));
        p = __fadd_rn( 0.00573950773f,  __fmul_rn(p, w));
        p = __fadd_rn(-0.0076224613f,   __fmul_rn(p, w));
        p = __fadd_rn( 0.00943887047f,  __fmul_rn(p, w));
        p = __fadd_rn( 1.00167406f,     __fmul_rn(p, w));
        p = __fadd_rn( 2.83297682f,     __fmul_rn(p, w));
    }
    return __fmul_rn(p, x);
}

__device__ __forceinline__ float bits_to_unit(unsigned bits) {
    return __uint_as_float((bits >> 9) | 0x3f800000u) - 1.0f;
}

// ---------------------------------------------------------------------
// RNG kernel (unchanged — bit-exact, ~5us)
// ---------------------------------------------------------------------
__global__ void ebsw_rng_kernel() {
    const int l = blockIdx.x;
    const int t = threadIdx.x;
    __shared__ float raw[BATCH * DIMS];

    uint2 kl = tf2x32(0u, 42u, 0u, (unsigned)l);
    uint2 ka, kb;
    if (l == 0) {
        ka = kl; kb = make_uint2(0u, 0u);
    } else {
#if PARTITIONABLE
        ka = tf2x32(kl.x, kl.y, 0u, 0u);
        kb = tf2x32(kl.x, kl.y, 0u, 1u);
#else
        uint2 p0 = tf2x32(kl.x, kl.y, 0u, 2u);
        uint2 p1 = tf2x32(kl.x, kl.y, 1u, 3u);
        ka = make_uint2(p0.x, p1.x);
        kb = make_uint2(p0.y, p1.y);
#endif
    }

    unsigned bits;
#if PARTITIONABLE
    { uint2 r = tf2x32(ka.x, ka.y, 0u, (unsigned)t); bits = r.x ^ r.y; }
#else
    if (t < 96) { uint2 r = tf2x32(ka.x, ka.y, (unsigned)t, (unsigned)(96 + t)); bits = r.x; }
    else        { uint2 r = tf2x32(ka.x, ka.y, (unsigned)(t - 96), (unsigned)t); bits = r.y; }
#endif
    const float LO = -0.99999994f;
    float f = bits_to_unit(bits);
    float u = __fadd_rn(__fmul_rn(f, 2.0f), LO);
    u = fmaxf(LO, u);
    raw[t] = __fmul_rn(1.41421356237309515f, xla_erfinv(u));
    __syncthreads();

    if (t < BATCH) {
        float v0 = raw[t * 3 + 0], v1 = raw[t * 3 + 1], v2 = raw[t * 3 + 2];
        float s  = __fadd_rn(__fadd_rn(__fmul_rn(v0, v0), __fmul_rn(v1, v1)),
                             __fmul_rn(v2, v2));
        float r  = __fsqrt_rn(s);
        g_theta[l][t][0] = __fdiv_rn(v0, r);
        g_theta[l][t][1] = __fdiv_rn(v1, r);
        g_theta[l][t][2] = __fdiv_rn(v2, r);

        if (l >= 1) {
            unsigned ub;
#if PARTITIONABLE
            { uint2 r2 = tf2x32(kb.x, kb.y, 0u, (unsigned)t); ub = r2.x ^ r2.y; }
#else
            if (t < 32) { uint2 r2 = tf2x32(kb.x, kb.y, (unsigned)t, (unsigned)(32 + t)); ub = r2.x; }
            else        { uint2 r2 = tf2x32(kb.x, kb.y, (unsigned)(t - 32), (unsigned)t); ub = r2.y; }
#endif
            g_logu[l][t] = logf(bits_to_unit(ub));
        }
    }
}

// ---------------------------------------------------------------------
// Distance kernel: V=32 elems/thread, 128 threads/array, 256 thr/CTA
// ---------------------------------------------------------------------
static const int TPB = 256;
static const int TPA = 128;    // threads per array
static const int V   = 32;     // elements per thread
static const int PAD = 33;     // padded row stride

__device__ __forceinline__ void cx(float& a, float& b, bool up) {
    // maps to predicated FMNMX pair
    float lo = up ? fminf(a, b) : fmaxf(a, b);
    float hi = up ? fmaxf(a, b) : fminf(a, b);
    a = lo; b = hi;
}

// intra-register merge, strides J..1, uniform direction per thread
template<int J>
__device__ __forceinline__ void merge_reg(float* r, bool up) {
    if constexpr (J >= 1) {
#pragma unroll
        for (int v = 0; v < V; ++v)
            if ((v & J) == 0) cx(r[v], r[v | J], up);
        merge_reg<J / 2>(r, up);
    }
}

// intra-register sort phase for block size K<=16: direction per element
template<int K, int J>
__device__ __forceinline__ void sort_reg_small(float* r) {
    if constexpr (J >= 1) {
#pragma unroll
        for (int v = 0; v < V; ++v)
            if ((v & J) == 0) cx(r[v], r[v | J], ((v & K) == 0));
        sort_reg_small<K, J / 2>(r);
    }
}

// cross-thread exchange at thread distance D (compile-time)
template<int D>
__device__ __forceinline__ void exchange_step(float* r, float* buf, int lt, bool up) {
    const bool keepmin = (((lt & D) == 0) == up);
    if constexpr (D < 32) {
#pragma unroll
        for (int v = 0; v < V; ++v) {
            float o = __shfl_xor_sync(0xffffffffu, r[v], D);
            r[v] = keepmin ? fminf(r[v], o) : fmaxf(r[v], o);
        }
    } else {
#pragma unroll
        for (int v = 0; v < V; ++v) buf[lt * PAD + v] = r[v];
        __syncthreads();
        const int p = (lt ^ D) * PAD;
#pragma unroll
        for (int v = 0; v < V; ++v) {
            float o = buf[p + v];
            r[v] = keepmin ? fminf(r[v], o) : fmaxf(r[v], o);
        }
        __syncthreads();
    }
}

// full merge: thread-level strides D..1, then intra-register strides
template<int D>
__device__ __forceinline__ void merge_chain(float* r, float* buf, int lt, bool up) {
    if constexpr (D >= 1) {
        exchange_step<D>(r, buf, lt, up);
        merge_chain<D / 2>(r, buf, lt, up);
    } else {
        merge_reg<V / 2>(r, up);
    }
}

__global__ __launch_bounds__(TPB) void ebsw_dist_kernel(
        const float* __restrict__ x, const float* __restrict__ y) {
    __shared__ float s[2 * TPA * PAD];   // 33,792 B
    const int blk = blockIdx.x;
    const int b = blk >> 7;
    const int l = blk & (LPROJ - 1);

    const float t0 = g_theta[l][b][0];
    const float t1 = g_theta[l][b][1];
    const float t2 = g_theta[l][b][2];

    const int tid = threadIdx.x;
    const int g   = tid >> 7;          // 0 -> x array, 1 -> y array
    const int lt  = tid & (TPA - 1);   // 0..127 within group
    float* buf = s + g * (TPA * PAD);

    // stage projections (coalesced within group), padded layout
    const float* pb = (g == 0 ? x : y) + (size_t)b * NPTS * DIMS;
    for (int n = lt; n < NPTS; n += TPA) {
        int o = n * 3;
        buf[(n >> 5) * PAD + (n & 31)] =
            fmaf(pb[o], t0, fmaf(pb[o + 1], t1, pb[o + 2] * t2));
    }
    __syncthreads();

    // load 32 contiguous elements: i = lt*32 + v
    float r[V];
#pragma unroll
    for (int v = 0; v < V; ++v) r[v] = buf[lt * PAD + v];
    __syncthreads();

    // ---- bitonic sort of 4096 = 128 threads x 32 regs ----
    sort_reg_small<2, 1>(r);
    sort_reg_small<4, 2>(r);
    sort_reg_small<8, 4>(r);
    sort_reg_small<16, 8>(r);
    { bool up = ((lt & 1)  == 0); merge_reg<V / 2>(r, up); }          // k=32
    { bool up = ((lt & 2)  == 0); merge_chain<1 >(r, buf, lt, up); }  // k=64
    { bool up = ((lt & 4)  == 0); merge_chain<2 >(r, buf, lt, up); }  // k=128
    { bool up = ((lt & 8)  == 0); merge_chain<4 >(r, buf, lt, up); }  // k=256
    { bool up = ((lt & 16) == 0); merge_chain<8 >(r, buf, lt, up); }  // k=512
    { bool up = ((lt & 32) == 0); merge_chain<16>(r, buf, lt, up); }  // k=1024
    { bool up = ((lt & 64) == 0); merge_chain<32>(r, buf, lt, up); }  // k=2048
    {                             merge_chain<64>(r, buf, lt, true); }// k=4096

    // write back sorted, rank-matched squared-diff reduce
#pragma unroll
    for (int v = 0; v < V; ++v) buf[lt * PAD + v] = r[v];
    __syncthreads();

    double acc = 0.0;
    for (int n = tid; n < NPTS; n += TPB) {
        int a = (n >> 5) * PAD + (n & 31);
        float d = s[a] - s[TPA * PAD + a];
        acc += (double)d * (double)d;
    }
#pragma unroll
    for (int off = 16; off; off >>= 1)
        acc += __shfl_down_sync(0xffffffffu, acc, off);
    __shared__ double wsum[TPB / 32];
    if ((threadIdx.x & 31) == 0) wsum[threadIdx.x >> 5] = acc;
    __syncthreads();
    if (threadIdx.x < TPB / 32) {
        double v = wsum[threadIdx.x];
#pragma unroll
        for (int off = (TPB / 32) / 2; off; off >>= 1)
            v += __shfl_down_sync(0xffu, v, off);
        if (threadIdx.x == 0) g_dist[b][l] = (float)v;
    }
}

// ---------------------------------------------------------------------
// Chain + loss kernel (unchanged)
// ---------------------------------------------------------------------
__global__ void ebsw_chain_kernel(float* __restrict__ out) {
    const int b = threadIdx.x;
    __shared__ double sh[BATCH];
    const float* db = g_dist[b];
    float dist_old = db[0];
    double acc = (double)dist_old;
    for (int l = 1; l < LPROJ; ++l) {
        float dn = db[l];
        float ar = fminf(0.0f, __fadd_rn(dn, -dist_old));
        if (g_logu[l][b] <= ar) dist_old = dn;
        acc += (double)dist_old;
    }
    sh[b] = sqrt(acc / (double)LPROJ);
    __syncthreads();
    if (b == 0) {
        double ssum = 0.0;
        for (int i = 0; i < BATCH; ++i) ssum += sh[i];
        out[0] = (float)(ssum / (double)BATCH);
    }
}

// ---------------------------------------------------------------------
extern "C" void kernel_launch(void* const* d_in, const int* in_sizes, int n_in,
                              void* d_out, int out_size) {
    const float* x = (const float*)d_in[0];
    const float* y = (const float*)d_in[1];
    float* out = (float*)d_out;

    ebsw_rng_kernel<<<LPROJ, BATCH * DIMS>>>();
    ebsw_dist_kernel<<<BATCH * LPROJ, TPB>>>(x, y);
    ebsw_chain_kernel<<<1, BATCH>>>(out);
}